// round 4
// baseline (speedup 1.0000x reference)
#include <cuda_runtime.h>
#include <cuda_fp16.h>
#include <cstdint>

// ============================================================================
// Problem constants
// ============================================================================
#define B_ROWS 262144
#define D_DIM  128
#define E_NUM  3
#define MAXT   2052

// ============================================================================
// Device-global scratch (no cudaMalloc allowed)
// ============================================================================
__device__ int   g_cnt[E_NUM];
__device__ int   g_cur[E_NUM];
__device__ int   g_idx[B_ROWS];
__device__ int   g_tile_e[MAXT];
__device__ int   g_tile_base[MAXT];
__device__ int   g_tile_m[MAXT];
__device__ int   g_ntiles;
__device__ __align__(16) __half g_wh[6 * 128 * 128];  // 6 weight mats, fp16 row-major

// ============================================================================
// Helpers
// ============================================================================
__device__ __forceinline__ uint32_t smem_to_u32(const void* smem_ptr) {
    uint32_t addr;
    asm("{ .reg .u64 tmp; cvta.to.shared.u64 tmp, %1; cvt.u32.u64 %0, tmp; }"
        : "=r"(addr) : "l"(smem_ptr));
    return addr;
}

__device__ __forceinline__ uint32_t pack_half2(float a, float b) {
    __half2 h = __floats2half2_rn(a, b);
    uint32_t u;
    memcpy(&u, &h, 4);
    return u;
}

#define LDMATRIX_X4(r0, r1, r2, r3, addr) \
    asm volatile("ldmatrix.sync.aligned.m8n8.x4.shared.b16 {%0,%1,%2,%3}, [%4];" \
        : "=r"(r0), "=r"(r1), "=r"(r2), "=r"(r3) : "r"(addr))

#define MMA16816(d, a0, a1, a2, a3, b0, b1) \
    asm volatile("mma.sync.aligned.m16n8k16.row.col.f32.f16.f16.f32 " \
        "{%0,%1,%2,%3}, {%4,%5,%6,%7}, {%8,%9}, {%0,%1,%2,%3};" \
        : "+f"((d)[0]), "+f"((d)[1]), "+f"((d)[2]), "+f"((d)[3]) \
        : "r"(a0), "r"(a1), "r"(a2), "r"(a3), "r"(b0), "r"(b1))

// ============================================================================
// Setup kernels
// ============================================================================
__global__ void k_reset() {
    int t = threadIdx.x;
    if (t < E_NUM) g_cnt[t] = 0;
}

__global__ void k_hist(const int* __restrict__ ch) {
    __shared__ int sc[E_NUM];
    int tid = threadIdx.x;
    if (tid < E_NUM) sc[tid] = 0;
    __syncthreads();
    int b = blockIdx.x * 256 + tid;
    atomicAdd(&sc[ch[b]], 1);
    __syncthreads();
    if (tid < E_NUM) atomicAdd(&g_cnt[tid], sc[tid]);
}

__global__ void k_plan() {
    int t = blockIdx.x * 1024 + threadIdx.x;
    int c0 = g_cnt[0], c1 = g_cnt[1], c2 = g_cnt[2];
    int n0 = (c0 + 127) >> 7, n1 = (c1 + 127) >> 7, n2 = (c2 + 127) >> 7;
    if (t == 0) {
        g_ntiles = n0 + n1 + n2;
        g_cur[0] = 0; g_cur[1] = c0; g_cur[2] = c0 + c1;
    }
    if (t < n0) {
        g_tile_e[t] = 0; g_tile_base[t] = t * 128;
        g_tile_m[t] = min(128, c0 - t * 128);
    } else if (t < n0 + n1) {
        int l = t - n0;
        g_tile_e[t] = 1; g_tile_base[t] = c0 + l * 128;
        g_tile_m[t] = min(128, c1 - l * 128);
    } else if (t < n0 + n1 + n2) {
        int l = t - n0 - n1;
        g_tile_e[t] = 2; g_tile_base[t] = c0 + c1 + l * 128;
        g_tile_m[t] = min(128, c2 - l * 128);
    }
}

__global__ void k_scatter(const int* __restrict__ ch) {
    __shared__ int sc[E_NUM], sbase[E_NUM];
    int tid = threadIdx.x;
    if (tid < E_NUM) sc[tid] = 0;
    __syncthreads();
    int b = blockIdx.x * 256 + tid;
    int e = ch[b];
    int local = atomicAdd(&sc[e], 1);
    __syncthreads();
    if (tid < E_NUM) sbase[tid] = atomicAdd(&g_cur[tid], sc[tid]);
    __syncthreads();
    g_idx[sbase[e] + local] = b;
}

// fp32 -> fp16 weight conversion, plain row-major [mat][o][d]
__global__ void k_wconv(const float* __restrict__ W1, const float* __restrict__ W2) {
    int i = blockIdx.x * 256 + threadIdx.x;   // 0..98303
    int mat = i >> 14;
    int r = i & 16383;
    int e = mat >> 1;
    const float* src = (mat & 1) ? W2 : W1;
    g_wh[i] = __float2half(src[e * 16384 + r]);
}

// ============================================================================
// Main fused MoE kernel: one CTA = one 128-row tile of one expert.
// 8 warps; warp w computes rows [16w, 16w+16). mma.sync m16n8k16.
// SMEM halves stride = 136 (272B rows) -> conflict-free ldmatrix.
// ============================================================================
#define STRIDE_B   272            // bytes per smem row (136 halves)
#define SM_GIDX    0              // 128 * 4B
#define SM_B1      512
#define SM_B2      1024
#define SM_XH      2048           // 128 x 272B = 34816
#define SM_W1      36864          // 34816
#define SM_W2      71680          // 34816
#define SMEM_TOTAL 106496

__global__ void __launch_bounds__(256, 2) k_moe(
    const float* __restrict__ x,
    const float* __restrict__ b1g,
    const float* __restrict__ b2g,
    const float* __restrict__ fresh,
    float* __restrict__ out)
{
    int t = blockIdx.x;
    if (t >= g_ntiles) return;

    extern __shared__ char smem[];
    uint32_t sb = smem_to_u32(smem);
    int tid  = threadIdx.x;
    int lane = tid & 31;
    int warp = tid >> 5;
    int wrow = warp * 16;

    int e    = g_tile_e[t];
    int base = g_tile_base[t];
    int m    = g_tile_m[t];

    // --- prologue: W1/W2 L2 -> smem (row-major 256B -> padded 272B rows) ---
    {
        const int4* ws1 = (const int4*)(g_wh + (e * 2 + 0) * 16384);
        const int4* ws2 = (const int4*)(g_wh + (e * 2 + 1) * 16384);
        #pragma unroll
        for (int i = tid; i < 2048; i += 256) {
            int row = i >> 4, ch = i & 15;
            *(int4*)(smem + SM_W1 + row * STRIDE_B + ch * 16) = ws1[i];
            *(int4*)(smem + SM_W2 + row * STRIDE_B + ch * 16) = ws2[i];
        }
    }
    // biases + gather indices into smem (threads 0-127)
    if (tid < 128) {
        ((float*)(smem + SM_B1))[tid] = b1g[e * 128 + tid];
        ((float*)(smem + SM_B2))[tid] = b2g[e * 128 + tid];
        ((int*)(smem + SM_GIDX))[tid] = (tid < m) ? g_idx[base + tid] : -1;
    }
    float factor = (fresh[e] > 0.f) ? 1.01f : 1.0f;

    // --- gather X rows -> fp16 -> smem XH. 2 threads per row, 64 floats each ---
    {
        int row  = tid >> 1;
        int half = tid & 1;
        int g = (row < m) ? g_idx[base + row] : -1;
        char* dst = smem + SM_XH + row * STRIDE_B + half * 128;
        if (g >= 0) {
            const float4* xr = ((const float4*)x) + (size_t)g * 32 + half * 16;
            #pragma unroll
            for (int i = 0; i < 16; i++) {
                float4 v = xr[i];
                uint2 p;
                p.x = pack_half2(v.x, v.y);
                p.y = pack_half2(v.z, v.w);
                *(uint2*)(dst + i * 8) = p;
            }
        } else {
            uint2 z; z.x = 0; z.y = 0;
            #pragma unroll
            for (int i = 0; i < 16; i++) *(uint2*)(dst + i * 8) = z;
        }
    }
    __syncthreads();

    // ldmatrix base addresses
    // A: lanes 0-7 rows 0-7 chunk0 | 8-15 rows 8-15 chunk0 | 16-23 rows 0-7 chunk1 | 24-31 rows 8-15 chunk1
    uint32_t a_base = sb + SM_XH + (uint32_t)(wrow + (lane & 15)) * STRIDE_B + (uint32_t)(lane >> 4) * 16;
    // B: lanes 0-7: n0-7 k-chunk0 | 8-15: n0-7 k-chunk1 | 16-23: n8-15 chunk0 | 24-31: n8-15 chunk1
    uint32_t b_row  = (uint32_t)(((lane >> 4) & 1) * 8 + (lane & 7));
    uint32_t b_coff = (uint32_t)(((lane >> 3) & 1) * 16);
    uint32_t b1_base = sb + SM_W1 + b_row * STRIDE_B + b_coff;
    uint32_t b2_base = sb + SM_W2 + b_row * STRIDE_B + b_coff;

    float acc[16][4];

    // ======================= layer 1 =======================
    #pragma unroll
    for (int j = 0; j < 16; j++)
        #pragma unroll
        for (int q = 0; q < 4; q++) acc[j][q] = 0.f;

    #pragma unroll
    for (int ks = 0; ks < 8; ks++) {
        uint32_t a0, a1, a2, a3;
        LDMATRIX_X4(a0, a1, a2, a3, a_base + ks * 32);
        #pragma unroll
        for (int jn = 0; jn < 8; jn++) {
            uint32_t r0, r1, r2, r3;
            LDMATRIX_X4(r0, r1, r2, r3, b1_base + (uint32_t)jn * (16 * STRIDE_B) + ks * 32);
            MMA16816(acc[2 * jn],     a0, a1, a2, a3, r0, r1);
            MMA16816(acc[2 * jn + 1], a0, a1, a2, a3, r2, r3);
        }
    }

    // --- epilogue 1: relu(+b1) -> half2 back into XH (same warp's rows) ---
    {
        const float* b1s = (const float*)(smem + SM_B1);
        int r0 = wrow + (lane >> 2);
        int c0 = 2 * (lane & 3);
        __syncwarp();
        #pragma unroll
        for (int j = 0; j < 16; j++) {
            int col = 8 * j + c0;
            float bb0 = b1s[col], bb1 = b1s[col + 1];
            uint32_t h01 = pack_half2(fmaxf(acc[j][0] + bb0, 0.f), fmaxf(acc[j][1] + bb1, 0.f));
            uint32_t h23 = pack_half2(fmaxf(acc[j][2] + bb0, 0.f), fmaxf(acc[j][3] + bb1, 0.f));
            *(uint32_t*)(smem + SM_XH + r0 * STRIDE_B + col * 2)       = h01;
            *(uint32_t*)(smem + SM_XH + (r0 + 8) * STRIDE_B + col * 2) = h23;
        }
        __syncwarp();
    }

    // ======================= layer 2 =======================
    #pragma unroll
    for (int j = 0; j < 16; j++)
        #pragma unroll
        for (int q = 0; q < 4; q++) acc[j][q] = 0.f;

    #pragma unroll
    for (int ks = 0; ks < 8; ks++) {
        uint32_t a0, a1, a2, a3;
        LDMATRIX_X4(a0, a1, a2, a3, a_base + ks * 32);
        #pragma unroll
        for (int jn = 0; jn < 8; jn++) {
            uint32_t r0, r1, r2, r3;
            LDMATRIX_X4(r0, r1, r2, r3, b2_base + (uint32_t)jn * (16 * STRIDE_B) + ks * 32);
            MMA16816(acc[2 * jn],     a0, a1, a2, a3, r0, r1);
            MMA16816(acc[2 * jn + 1], a0, a1, a2, a3, r2, r3);
        }
    }

    // --- epilogue 2: relu(+b2)*factor -> scatter straight to gmem (v2.f32) ---
    {
        const float* b2s = (const float*)(smem + SM_B2);
        const int* gix = (const int*)(smem + SM_GIDX);
        int r0 = wrow + (lane >> 2);
        int c0 = 2 * (lane & 3);
        int g0 = gix[r0];
        int g1 = gix[r0 + 8];
        #pragma unroll
        for (int j = 0; j < 16; j++) {
            int col = 8 * j + c0;
            float bb0 = b2s[col], bb1 = b2s[col + 1];
            if (g0 >= 0) {
                float2 o;
                o.x = fmaxf(acc[j][0] + bb0, 0.f) * factor;
                o.y = fmaxf(acc[j][1] + bb1, 0.f) * factor;
                *(float2*)(out + (size_t)g0 * 128 + col) = o;
            }
            if (g1 >= 0) {
                float2 o;
                o.x = fmaxf(acc[j][2] + bb0, 0.f) * factor;
                o.y = fmaxf(acc[j][3] + bb1, 0.f) * factor;
                *(float2*)(out + (size_t)g1 * 128 + col) = o;
            }
        }
    }
}

// ============================================================================
// Launcher
// ============================================================================
extern "C" void kernel_launch(void* const* d_in, const int* in_sizes, int n_in,
                              void* d_out, int out_size) {
    const float* x      = (const float*)d_in[0];
    const float* W1     = (const float*)d_in[1];
    const float* b1     = (const float*)d_in[2];
    const float* W2     = (const float*)d_in[3];
    const float* b2     = (const float*)d_in[4];
    const float* fresh  = (const float*)d_in[5];
    const int*   chosen = (const int*)d_in[6];
    float* out = (float*)d_out;

    cudaFuncSetAttribute(k_moe, cudaFuncAttributeMaxDynamicSharedMemorySize, SMEM_TOTAL);

    k_reset<<<1, 32>>>();
    k_hist<<<B_ROWS / 256, 256>>>(chosen);
    k_plan<<<3, 1024>>>();
    k_scatter<<<B_ROWS / 256, 256>>>(chosen);
    k_wconv<<<384, 256>>>(W1, W2);
    k_moe<<<MAXT, 256, SMEM_TOTAL>>>(x, b1, b2, fresh, out);
}

// round 5
// speedup vs baseline: 1.5431x; 1.5431x over previous
#include <cuda_runtime.h>
#include <cuda_fp16.h>
#include <cstdint>

// ============================================================================
// Problem constants
// ============================================================================
#define B_ROWS 262144
#define D_DIM  128
#define E_NUM  3
#define MAXT   2052
#define NCTA   296          // 2 CTAs per SM on 148-SM B200

// ============================================================================
// Device-global scratch (no cudaMalloc allowed)
// ============================================================================
__device__ int   g_cnt[E_NUM];
__device__ int   g_idx_e[E_NUM][B_ROWS];     // per-expert row lists
__device__ int   g_tile_e[MAXT];
__device__ int   g_tile_base[MAXT];          // local base within expert list
__device__ int   g_tile_m[MAXT];
__device__ int   g_ntiles;
__device__ __align__(16) __half g_wh[6 * 128 * 128];  // 6 weight mats, fp16 row-major

// ============================================================================
// Helpers
// ============================================================================
__device__ __forceinline__ uint32_t smem_to_u32(const void* smem_ptr) {
    uint32_t addr;
    asm("{ .reg .u64 tmp; cvta.to.shared.u64 tmp, %1; cvt.u32.u64 %0, tmp; }"
        : "=r"(addr) : "l"(smem_ptr));
    return addr;
}

__device__ __forceinline__ uint32_t pack_half2(float a, float b) {
    __half2 h = __floats2half2_rn(a, b);
    uint32_t u;
    memcpy(&u, &h, 4);
    return u;
}

#define LDMATRIX_X4(r0, r1, r2, r3, addr) \
    asm volatile("ldmatrix.sync.aligned.m8n8.x4.shared.b16 {%0,%1,%2,%3}, [%4];" \
        : "=r"(r0), "=r"(r1), "=r"(r2), "=r"(r3) : "r"(addr))

#define MMA16816(d, a0, a1, a2, a3, b0, b1) \
    asm volatile("mma.sync.aligned.m16n8k16.row.col.f32.f16.f16.f32 " \
        "{%0,%1,%2,%3}, {%4,%5,%6,%7}, {%8,%9}, {%0,%1,%2,%3};" \
        : "+f"((d)[0]), "+f"((d)[1]), "+f"((d)[2]), "+f"((d)[3]) \
        : "r"(a0), "r"(a1), "r"(a2), "r"(a3), "r"(b0), "r"(b1))

// ============================================================================
// Setup kernels
// ============================================================================
__global__ void k_reset() {
    int t = threadIdx.x;
    if (t < E_NUM) g_cnt[t] = 0;
}

// Single-pass routing: block-aggregated slot reservation per expert.
// Order within an expert is nondeterministic, but the final output is
// order-invariant (each row computed identically wherever it lands).
__global__ void k_route(const int* __restrict__ ch) {
    __shared__ int sc[E_NUM], sbase[E_NUM];
    int tid = threadIdx.x;
    if (tid < E_NUM) sc[tid] = 0;
    __syncthreads();
    int b = blockIdx.x * 256 + tid;
    int e = ch[b];
    int local = atomicAdd(&sc[e], 1);
    __syncthreads();
    if (tid < E_NUM) sbase[tid] = atomicAdd(&g_cnt[tid], sc[tid]);
    __syncthreads();
    g_idx_e[e][sbase[e] + local] = b;
}

__global__ void k_plan() {
    int t = blockIdx.x * 1024 + threadIdx.x;
    int c0 = g_cnt[0], c1 = g_cnt[1], c2 = g_cnt[2];
    int n0 = (c0 + 127) >> 7, n1 = (c1 + 127) >> 7, n2 = (c2 + 127) >> 7;
    if (t == 0) g_ntiles = n0 + n1 + n2;
    if (t < n0) {
        g_tile_e[t] = 0; g_tile_base[t] = t * 128;
        g_tile_m[t] = min(128, c0 - t * 128);
    } else if (t < n0 + n1) {
        int l = t - n0;
        g_tile_e[t] = 1; g_tile_base[t] = l * 128;
        g_tile_m[t] = min(128, c1 - l * 128);
    } else if (t < n0 + n1 + n2) {
        int l = t - n0 - n1;
        g_tile_e[t] = 2; g_tile_base[t] = l * 128;
        g_tile_m[t] = min(128, c2 - l * 128);
    }
}

// fp32 -> fp16 weight conversion, row-major [mat][o][d]
__global__ void k_wconv(const float* __restrict__ W1, const float* __restrict__ W2) {
    int i = blockIdx.x * 256 + threadIdx.x;   // 0..98303
    int mat = i >> 14;
    int r = i & 16383;
    int e = mat >> 1;
    const float* src = (mat & 1) ? W2 : W1;
    g_wh[i] = __float2half(src[e * 16384 + r]);
}

// ============================================================================
// Persistent fused MoE kernel.
// 8 warps / CTA; warp w owns rows [16w,16w+16) of each 128-row tile.
// A operands (X, then H) live entirely in registers; W1/W2 in smem (ldmatrix).
// No per-tile __syncthreads -> warps free-run and overlap gather with MMA.
// ============================================================================
#define STRIDE_B   272            // bytes per smem weight row (136 halves)
#define SM_B1      0
#define SM_B2      512
#define SM_W1      1024           // 128 x 272B = 34816
#define SM_W2      35840
#define SMEM_TOTAL 70656

__global__ void __launch_bounds__(256, 2) k_moe(
    const float* __restrict__ x,
    const float* __restrict__ b1g,
    const float* __restrict__ b2g,
    const float* __restrict__ fresh,
    float* __restrict__ out)
{
    extern __shared__ char smem[];
    uint32_t sb = smem_to_u32(smem);
    int tid  = threadIdx.x;
    int lane = tid & 31;
    int warp = tid >> 5;

    int ntiles = g_ntiles;
    int chunk  = (ntiles + NCTA - 1) / NCTA;
    int t0 = blockIdx.x * chunk;
    int t1 = min(ntiles, t0 + chunk);
    if (t0 >= t1) return;

    // per-thread fragment geometry
    int rA = warp * 16 + (lane >> 2);     // A rows this thread covers
    int c0 = 2 * (lane & 3);              // fragment column pair base

    // ldmatrix B addressing (validated layout from R4)
    uint32_t b_row  = (uint32_t)(((lane >> 4) & 1) * 8 + (lane & 7));
    uint32_t b_coff = (uint32_t)(((lane >> 3) & 1) * 16);
    uint32_t b1_base = sb + SM_W1 + b_row * STRIDE_B + b_coff;
    uint32_t b2_base = sb + SM_W2 + b_row * STRIDE_B + b_coff;

    const float* b1s = (const float*)(smem + SM_B1);
    const float* b2s = (const float*)(smem + SM_B2);

    int cur_e = -1;
    float factor = 1.0f;

    for (int t = t0; t < t1; t++) {
        int e = g_tile_e[t];
        if (e != cur_e) {
            __syncthreads();   // drain warps still reading old W
            const int4* ws1 = (const int4*)(g_wh + (e * 2 + 0) * 16384);
            const int4* ws2 = (const int4*)(g_wh + (e * 2 + 1) * 16384);
            #pragma unroll
            for (int i = tid; i < 2048; i += 256) {
                int row = i >> 4, ch = i & 15;
                *(int4*)(smem + SM_W1 + row * STRIDE_B + ch * 16) = ws1[i];
                *(int4*)(smem + SM_W2 + row * STRIDE_B + ch * 16) = ws2[i];
            }
            if (tid < 128) {
                ((float*)(smem + SM_B1))[tid] = b1g[e * 128 + tid];
                ((float*)(smem + SM_B2))[tid] = b2g[e * 128 + tid];
            }
            factor = (fresh[e] > 0.f) ? 1.01f : 1.0f;
            cur_e = e;
            __syncthreads();
        }

        int lbase = g_tile_base[t];
        int m     = g_tile_m[t];
        const int* idxp = g_idx_e[e];
        int gA = (rA < m)     ? idxp[lbase + rA]     : -1;
        int gB = (rA + 8 < m) ? idxp[lbase + rA + 8] : -1;

        // --- gather X directly into A-fragment registers ---
        // Ah[4ks+0]=a0 (rowA,k0-7)  Ah[4ks+1]=a2 (rowA,k8-15)
        // Ah[4ks+2]=a1 (rowB,k0-7)  Ah[4ks+3]=a3 (rowB,k8-15)
        uint32_t Ah[32];
        if (gA >= 0) {
            const float* pA = x + (size_t)gA * 128 + c0;
            #pragma unroll
            for (int ks = 0; ks < 8; ks++) {
                float2 v0 = *(const float2*)(pA + 16 * ks);
                float2 v1 = *(const float2*)(pA + 16 * ks + 8);
                Ah[4 * ks]     = pack_half2(v0.x, v0.y);
                Ah[4 * ks + 1] = pack_half2(v1.x, v1.y);
            }
        } else {
            #pragma unroll
            for (int ks = 0; ks < 8; ks++) { Ah[4 * ks] = 0; Ah[4 * ks + 1] = 0; }
        }
        if (gB >= 0) {
            const float* pB = x + (size_t)gB * 128 + c0;
            #pragma unroll
            for (int ks = 0; ks < 8; ks++) {
                float2 v0 = *(const float2*)(pB + 16 * ks);
                float2 v1 = *(const float2*)(pB + 16 * ks + 8);
                Ah[4 * ks + 2] = pack_half2(v0.x, v0.y);
                Ah[4 * ks + 3] = pack_half2(v1.x, v1.y);
            }
        } else {
            #pragma unroll
            for (int ks = 0; ks < 8; ks++) { Ah[4 * ks + 2] = 0; Ah[4 * ks + 3] = 0; }
        }

        float acc[16][4];

        // ======================= layer 1 =======================
        #pragma unroll
        for (int j = 0; j < 16; j++)
            #pragma unroll
            for (int q = 0; q < 4; q++) acc[j][q] = 0.f;

        #pragma unroll
        for (int ks = 0; ks < 8; ks++) {
            #pragma unroll
            for (int jn = 0; jn < 8; jn++) {
                uint32_t r0, r1, r2, r3;
                LDMATRIX_X4(r0, r1, r2, r3, b1_base + (uint32_t)jn * (16 * STRIDE_B) + ks * 32);
                MMA16816(acc[2 * jn],     Ah[4 * ks], Ah[4 * ks + 2], Ah[4 * ks + 1], Ah[4 * ks + 3], r0, r1);
                MMA16816(acc[2 * jn + 1], Ah[4 * ks], Ah[4 * ks + 2], Ah[4 * ks + 1], Ah[4 * ks + 3], r2, r3);
            }
        }

        // --- epilogue 1: relu(+b1) -> layer-2 A fragments, pure registers ---
        // H[rA][16ks+c0..+1]   = relu(acc[2ks][0..1])   -> a0
        // H[rB][16ks+c0..+1]   = relu(acc[2ks][2..3])   -> a1
        // H[rA][16ks+8+c0..+1] = relu(acc[2ks+1][0..1]) -> a2
        // H[rB][16ks+8+c0..+1] = relu(acc[2ks+1][2..3]) -> a3
        #pragma unroll
        for (int ks = 0; ks < 8; ks++) {
            float2 bb0 = *(const float2*)(b1s + 16 * ks + c0);
            float2 bb1 = *(const float2*)(b1s + 16 * ks + 8 + c0);
            Ah[4 * ks]     = pack_half2(fmaxf(acc[2 * ks][0]     + bb0.x, 0.f), fmaxf(acc[2 * ks][1]     + bb0.y, 0.f));
            Ah[4 * ks + 2] = pack_half2(fmaxf(acc[2 * ks][2]     + bb0.x, 0.f), fmaxf(acc[2 * ks][3]     + bb0.y, 0.f));
            Ah[4 * ks + 1] = pack_half2(fmaxf(acc[2 * ks + 1][0] + bb1.x, 0.f), fmaxf(acc[2 * ks + 1][1] + bb1.y, 0.f));
            Ah[4 * ks + 3] = pack_half2(fmaxf(acc[2 * ks + 1][2] + bb1.x, 0.f), fmaxf(acc[2 * ks + 1][3] + bb1.y, 0.f));
        }

        // ======================= layer 2 =======================
        #pragma unroll
        for (int j = 0; j < 16; j++)
            #pragma unroll
            for (int q = 0; q < 4; q++) acc[j][q] = 0.f;

        #pragma unroll
        for (int ks = 0; ks < 8; ks++) {
            #pragma unroll
            for (int jn = 0; jn < 8; jn++) {
                uint32_t r0, r1, r2, r3;
                LDMATRIX_X4(r0, r1, r2, r3, b2_base + (uint32_t)jn * (16 * STRIDE_B) + ks * 32);
                MMA16816(acc[2 * jn],     Ah[4 * ks], Ah[4 * ks + 2], Ah[4 * ks + 1], Ah[4 * ks + 3], r0, r1);
                MMA16816(acc[2 * jn + 1], Ah[4 * ks], Ah[4 * ks + 2], Ah[4 * ks + 1], Ah[4 * ks + 3], r2, r3);
            }
        }

        // --- epilogue 2: relu(+b2)*factor -> scatter straight from registers ---
        {
            float f = factor;
            #pragma unroll
            for (int j = 0; j < 16; j++) {
                int col = 8 * j + c0;
                float2 bb = *(const float2*)(b2s + col);
                if (gA >= 0) {
                    float2 o;
                    o.x = fmaxf(acc[j][0] + bb.x, 0.f) * f;
                    o.y = fmaxf(acc[j][1] + bb.y, 0.f) * f;
                    *(float2*)(out + (size_t)gA * 128 + col) = o;
                }
                if (gB >= 0) {
                    float2 o;
                    o.x = fmaxf(acc[j][2] + bb.x, 0.f) * f;
                    o.y = fmaxf(acc[j][3] + bb.y, 0.f) * f;
                    *(float2*)(out + (size_t)gB * 128 + col) = o;
                }
            }
        }
    }
}

// ============================================================================
// Launcher
// ============================================================================
extern "C" void kernel_launch(void* const* d_in, const int* in_sizes, int n_in,
                              void* d_out, int out_size) {
    const float* x      = (const float*)d_in[0];
    const float* W1     = (const float*)d_in[1];
    const float* b1     = (const float*)d_in[2];
    const float* W2     = (const float*)d_in[3];
    const float* b2     = (const float*)d_in[4];
    const float* fresh  = (const float*)d_in[5];
    const int*   chosen = (const int*)d_in[6];
    float* out = (float*)d_out;

    cudaFuncSetAttribute(k_moe, cudaFuncAttributeMaxDynamicSharedMemorySize, SMEM_TOTAL);

    k_reset<<<1, 32>>>();
    k_route<<<B_ROWS / 256, 256>>>(chosen);
    k_plan<<<3, 1024>>>();
    k_wconv<<<384, 256>>>(W1, W2);
    k_moe<<<NCTA, 256, SMEM_TOTAL>>>(x, b1, b2, fresh, out);
}

// round 6
// speedup vs baseline: 1.6133x; 1.0455x over previous
#include <cuda_runtime.h>
#include <cuda_fp16.h>
#include <cstdint>

// ============================================================================
// Problem constants
// ============================================================================
#define B_ROWS 262144
#define D_DIM  128
#define E_NUM  3
#define NCTA   296          // 2 CTAs per SM on 148-SM B200

// ============================================================================
// Device-global scratch (no cudaMalloc allowed)
// ============================================================================
__device__ int   g_cnt[E_NUM];
__device__ int   g_idx_e[E_NUM][B_ROWS];     // per-expert row lists
__device__ __align__(16) __half g_wh[6 * 128 * 128];  // 6 weight mats, fp16 row-major

// ============================================================================
// Helpers
// ============================================================================
__device__ __forceinline__ uint32_t smem_to_u32(const void* smem_ptr) {
    uint32_t addr;
    asm("{ .reg .u64 tmp; cvta.to.shared.u64 tmp, %1; cvt.u32.u64 %0, tmp; }"
        : "=r"(addr) : "l"(smem_ptr));
    return addr;
}

__device__ __forceinline__ uint32_t pack_half2(float a, float b) {
    __half2 h = __floats2half2_rn(a, b);
    uint32_t u;
    memcpy(&u, &h, 4);
    return u;
}

#define LDMATRIX_X4(r0, r1, r2, r3, addr) \
    asm volatile("ldmatrix.sync.aligned.m8n8.x4.shared.b16 {%0,%1,%2,%3}, [%4];" \
        : "=r"(r0), "=r"(r1), "=r"(r2), "=r"(r3) : "r"(addr))

#define MMA16816(d, a0, a1, a2, a3, b0, b1) \
    asm volatile("mma.sync.aligned.m16n8k16.row.col.f32.f16.f16.f32 " \
        "{%0,%1,%2,%3}, {%4,%5,%6,%7}, {%8,%9}, {%0,%1,%2,%3};" \
        : "+f"((d)[0]), "+f"((d)[1]), "+f"((d)[2]), "+f"((d)[3]) \
        : "r"(a0), "r"(a1), "r"(a2), "r"(a3), "r"(b0), "r"(b1))

// ============================================================================
// Setup kernels
// ============================================================================

// fp32 -> fp16 weight conversion (4 elems/thread) + g_cnt reset.
__global__ void k_wconv(const float* __restrict__ W1, const float* __restrict__ W2) {
    if (blockIdx.x == 0 && threadIdx.x < E_NUM) g_cnt[threadIdx.x] = 0;
    int i = blockIdx.x * 256 + threadIdx.x;   // 0..24575
    int base = i * 4;
    int mat = base >> 14;
    int r = base & 16383;
    int e = mat >> 1;
    const float* src = (mat & 1) ? W2 : W1;
    float4 v = *(const float4*)(src + e * 16384 + r);
    uint2 o;
    o.x = pack_half2(v.x, v.y);
    o.y = pack_half2(v.z, v.w);
    *(uint2*)(g_wh + base) = o;
}

// Single-pass routing: block-aggregated slot reservation per expert.
// Order within an expert is nondeterministic; output is order-invariant.
__global__ void k_route(const int* __restrict__ ch) {
    __shared__ int sc[E_NUM], sbase[E_NUM];
    int tid = threadIdx.x;
    if (tid < E_NUM) sc[tid] = 0;
    __syncthreads();
    int b = blockIdx.x * 256 + tid;
    int e = ch[b];
    int local = atomicAdd(&sc[e], 1);
    __syncthreads();
    if (tid < E_NUM) sbase[tid] = atomicAdd(&g_cnt[tid], sc[tid]);
    __syncthreads();
    g_idx_e[e][sbase[e] + local] = b;
}

// ============================================================================
// Persistent fused MoE kernel.
// 4 warps / CTA; warp w owns rows [32w, 32w+32) of each 128-row tile.
// Doubling M per warp halves ldmatrix weight traffic (B frags reused 2x).
// A operands (X, then H) fully register-resident; no per-tile syncthreads.
// ============================================================================
#define STRIDE_B   272            // bytes per smem weight row (136 halves)
#define SM_B1      0
#define SM_B2      512
#define SM_W1      1024           // 128 x 272B = 34816
#define SM_W2      35840
#define SMEM_TOTAL 70656

__global__ void __launch_bounds__(128, 2) k_moe(
    const float* __restrict__ x,
    const float* __restrict__ b1g,
    const float* __restrict__ b2g,
    const float* __restrict__ fresh,
    float* __restrict__ out)
{
    extern __shared__ char smem[];
    uint32_t sb = smem_to_u32(smem);
    int tid  = threadIdx.x;
    int lane = tid & 31;
    int warp = tid >> 5;

    // inline tile plan from g_cnt
    int cn0 = g_cnt[0], cn1 = g_cnt[1], cn2 = g_cnt[2];
    int n0 = (cn0 + 127) >> 7, n1 = (cn1 + 127) >> 7, n2 = (cn2 + 127) >> 7;
    int ntiles = n0 + n1 + n2;

    int chunk = (ntiles + NCTA - 1) / NCTA;
    int t0 = blockIdx.x * chunk;
    int t1 = min(ntiles, t0 + chunk);
    if (t0 >= t1) return;

    int qrow = lane >> 2;                 // 0..7
    int c0   = 2 * (lane & 3);            // fragment column pair base

    // ldmatrix B addressing (layout validated in R4/R5)
    uint32_t b_row  = (uint32_t)(((lane >> 4) & 1) * 8 + (lane & 7));
    uint32_t b_coff = (uint32_t)(((lane >> 3) & 1) * 16);
    uint32_t b1_base = sb + SM_W1 + b_row * STRIDE_B + b_coff;
    uint32_t b2_base = sb + SM_W2 + b_row * STRIDE_B + b_coff;

    const float* b1s = (const float*)(smem + SM_B1);
    const float* b2s = (const float*)(smem + SM_B2);

    int cur_e = -1;
    float factor = 1.0f;

    for (int t = t0; t < t1; t++) {
        // tile -> (expert, local base, rows)
        int e, l, cnt;
        if (t < n0)           { e = 0; l = t;            cnt = cn0; }
        else if (t < n0 + n1) { e = 1; l = t - n0;       cnt = cn1; }
        else                  { e = 2; l = t - n0 - n1;  cnt = cn2; }
        int lbase = l * 128;
        int m = min(128, cnt - lbase);

        if (e != cur_e) {
            __syncthreads();   // drain warps still reading old W
            const int4* ws1 = (const int4*)(g_wh + (e * 2 + 0) * 16384);
            const int4* ws2 = (const int4*)(g_wh + (e * 2 + 1) * 16384);
            #pragma unroll
            for (int i = tid; i < 2048; i += 128) {
                int row = i >> 4, ch = i & 15;
                *(int4*)(smem + SM_W1 + row * STRIDE_B + ch * 16) = ws1[i];
                *(int4*)(smem + SM_W2 + row * STRIDE_B + ch * 16) = ws2[i];
            }
            if (tid < 128) {
                ((float*)(smem + SM_B1))[tid] = b1g[e * 128 + tid];
                ((float*)(smem + SM_B2))[tid] = b2g[e * 128 + tid];
            }
            factor = (fresh[e] > 0.f) ? 1.01f : 1.0f;
            cur_e = e;
            __syncthreads();
        }

        const int* idxp = g_idx_e[e] + lbase;
        // 4 rows per thread: rowgroup R in {0,1}, A-row and B-row (+8)
        int rA0 = warp * 32 + qrow;
        int g0 = (rA0 < m)      ? idxp[rA0]      : -1;   // R0 rowA
        int g1 = (rA0 + 8 < m)  ? idxp[rA0 + 8]  : -1;   // R0 rowB
        int g2 = (rA0 + 16 < m) ? idxp[rA0 + 16] : -1;   // R1 rowA
        int g3 = (rA0 + 24 < m) ? idxp[rA0 + 24] : -1;   // R1 rowB

        // --- gather X into A fragments. Xh[R][4ks+{0,1}]=rowA k-lo/hi,
        //     [4ks+{2,3}]=rowB k-lo/hi ---
        uint32_t Xh[2][32];
        {
            int gs[4] = {g0, g1, g2, g3};
            #pragma unroll
            for (int rr = 0; rr < 4; rr++) {
                int R = rr >> 1, o = (rr & 1) * 2;
                int g = gs[rr];
                if (g >= 0) {
                    const float* p = x + (size_t)g * 128 + c0;
                    #pragma unroll
                    for (int ks = 0; ks < 8; ks++) {
                        float2 v0 = *(const float2*)(p + 16 * ks);
                        float2 v1 = *(const float2*)(p + 16 * ks + 8);
                        Xh[R][4 * ks + o]     = pack_half2(v0.x, v0.y);
                        Xh[R][4 * ks + o + 1] = pack_half2(v1.x, v1.y);
                    }
                } else {
                    #pragma unroll
                    for (int ks = 0; ks < 8; ks++) {
                        Xh[R][4 * ks + o] = 0;
                        Xh[R][4 * ks + o + 1] = 0;
                    }
                }
            }
        }

        // ======================= layer 1 -> Hh =======================
        uint32_t Hh[2][32];
        #pragma unroll
        for (int jn = 0; jn < 8; jn++) {
            float acc[4][4];      // [R*2 + nhalf][4]
            #pragma unroll
            for (int q = 0; q < 4; q++) {
                acc[0][q] = 0.f; acc[1][q] = 0.f; acc[2][q] = 0.f; acc[3][q] = 0.f;
            }
            #pragma unroll
            for (int ks = 0; ks < 8; ks++) {
                uint32_t r0, r1, r2, r3;
                LDMATRIX_X4(r0, r1, r2, r3, b1_base + (uint32_t)jn * (16 * STRIDE_B) + ks * 32);
                MMA16816(acc[0], Xh[0][4 * ks], Xh[0][4 * ks + 2], Xh[0][4 * ks + 1], Xh[0][4 * ks + 3], r0, r1);
                MMA16816(acc[1], Xh[0][4 * ks], Xh[0][4 * ks + 2], Xh[0][4 * ks + 1], Xh[0][4 * ks + 3], r2, r3);
                MMA16816(acc[2], Xh[1][4 * ks], Xh[1][4 * ks + 2], Xh[1][4 * ks + 1], Xh[1][4 * ks + 3], r0, r1);
                MMA16816(acc[3], Xh[1][4 * ks], Xh[1][4 * ks + 2], Xh[1][4 * ks + 1], Xh[1][4 * ks + 3], r2, r3);
            }
            // epilogue: relu(+b1) -> layer-2 A fragments (k-group jn)
            float2 bb0 = *(const float2*)(b1s + 16 * jn + c0);
            float2 bb1 = *(const float2*)(b1s + 16 * jn + 8 + c0);
            #pragma unroll
            for (int R = 0; R < 2; R++) {
                Hh[R][4 * jn]     = pack_half2(fmaxf(acc[2 * R][0] + bb0.x, 0.f),
                                               fmaxf(acc[2 * R][1] + bb0.y, 0.f));
                Hh[R][4 * jn + 1] = pack_half2(fmaxf(acc[2 * R + 1][0] + bb1.x, 0.f),
                                               fmaxf(acc[2 * R + 1][1] + bb1.y, 0.f));
                Hh[R][4 * jn + 2] = pack_half2(fmaxf(acc[2 * R][2] + bb0.x, 0.f),
                                               fmaxf(acc[2 * R][3] + bb0.y, 0.f));
                Hh[R][4 * jn + 3] = pack_half2(fmaxf(acc[2 * R + 1][2] + bb1.x, 0.f),
                                               fmaxf(acc[2 * R + 1][3] + bb1.y, 0.f));
            }
        }

        // ======================= layer 2 -> gmem =======================
        float f = factor;
        #pragma unroll
        for (int jn = 0; jn < 8; jn++) {
            float acc[4][4];
            #pragma unroll
            for (int q = 0; q < 4; q++) {
                acc[0][q] = 0.f; acc[1][q] = 0.f; acc[2][q] = 0.f; acc[3][q] = 0.f;
            }
            #pragma unroll
            for (int ks = 0; ks < 8; ks++) {
                uint32_t r0, r1, r2, r3;
                LDMATRIX_X4(r0, r1, r2, r3, b2_base + (uint32_t)jn * (16 * STRIDE_B) + ks * 32);
                MMA16816(acc[0], Hh[0][4 * ks], Hh[0][4 * ks + 2], Hh[0][4 * ks + 1], Hh[0][4 * ks + 3], r0, r1);
                MMA16816(acc[1], Hh[0][4 * ks], Hh[0][4 * ks + 2], Hh[0][4 * ks + 1], Hh[0][4 * ks + 3], r2, r3);
                MMA16816(acc[2], Hh[1][4 * ks], Hh[1][4 * ks + 2], Hh[1][4 * ks + 1], Hh[1][4 * ks + 3], r0, r1);
                MMA16816(acc[3], Hh[1][4 * ks], Hh[1][4 * ks + 2], Hh[1][4 * ks + 1], Hh[1][4 * ks + 3], r2, r3);
            }
            // epilogue: relu(+b2)*factor -> scatter from registers
            int col0 = 16 * jn + c0;
            int col1 = col0 + 8;
            float2 bb0 = *(const float2*)(b2s + col0);
            float2 bb1 = *(const float2*)(b2s + col1);
            if (g0 >= 0) {
                float2 o;
                o.x = fmaxf(acc[0][0] + bb0.x, 0.f) * f;
                o.y = fmaxf(acc[0][1] + bb0.y, 0.f) * f;
                *(float2*)(out + (size_t)g0 * 128 + col0) = o;
                o.x = fmaxf(acc[1][0] + bb1.x, 0.f) * f;
                o.y = fmaxf(acc[1][1] + bb1.y, 0.f) * f;
                *(float2*)(out + (size_t)g0 * 128 + col1) = o;
            }
            if (g1 >= 0) {
                float2 o;
                o.x = fmaxf(acc[0][2] + bb0.x, 0.f) * f;
                o.y = fmaxf(acc[0][3] + bb0.y, 0.f) * f;
                *(float2*)(out + (size_t)g1 * 128 + col0) = o;
                o.x = fmaxf(acc[1][2] + bb1.x, 0.f) * f;
                o.y = fmaxf(acc[1][3] + bb1.y, 0.f) * f;
                *(float2*)(out + (size_t)g1 * 128 + col1) = o;
            }
            if (g2 >= 0) {
                float2 o;
                o.x = fmaxf(acc[2][0] + bb0.x, 0.f) * f;
                o.y = fmaxf(acc[2][1] + bb0.y, 0.f) * f;
                *(float2*)(out + (size_t)g2 * 128 + col0) = o;
                o.x = fmaxf(acc[3][0] + bb1.x, 0.f) * f;
                o.y = fmaxf(acc[3][1] + bb1.y, 0.f) * f;
                *(float2*)(out + (size_t)g2 * 128 + col1) = o;
            }
            if (g3 >= 0) {
                float2 o;
                o.x = fmaxf(acc[2][2] + bb0.x, 0.f) * f;
                o.y = fmaxf(acc[2][3] + bb0.y, 0.f) * f;
                *(float2*)(out + (size_t)g3 * 128 + col0) = o;
                o.x = fmaxf(acc[3][2] + bb1.x, 0.f) * f;
                o.y = fmaxf(acc[3][3] + bb1.y, 0.f) * f;
                *(float2*)(out + (size_t)g3 * 128 + col1) = o;
            }
        }
    }
}

// ============================================================================
// Launcher
// ============================================================================
extern "C" void kernel_launch(void* const* d_in, const int* in_sizes, int n_in,
                              void* d_out, int out_size) {
    const float* x      = (const float*)d_in[0];
    const float* W1     = (const float*)d_in[1];
    const float* b1     = (const float*)d_in[2];
    const float* W2     = (const float*)d_in[3];
    const float* b2     = (const float*)d_in[4];
    const float* fresh  = (const float*)d_in[5];
    const int*   chosen = (const int*)d_in[6];
    float* out = (float*)d_out;

    cudaFuncSetAttribute(k_moe, cudaFuncAttributeMaxDynamicSharedMemorySize, SMEM_TOTAL);

    k_wconv<<<96, 256>>>(W1, W2);          // also resets g_cnt
    k_route<<<B_ROWS / 256, 256>>>(chosen);
    k_moe<<<NCTA, 128, SMEM_TOTAL>>>(x, b1, b2, fresh, out);
}

// round 7
// speedup vs baseline: 1.6395x; 1.0162x over previous
#include <cuda_runtime.h>
#include <cuda_fp16.h>
#include <cstdint>

// ============================================================================
// Problem constants
// ============================================================================
#define B_ROWS 262144
#define D_DIM  128
#define E_NUM  3
#define NCTA   296          // 2 CTAs per SM on 148-SM B200

// ============================================================================
// Device-global scratch (no cudaMalloc allowed)
// ============================================================================
__device__ int   g_cnt[E_NUM];
__device__ int   g_idx_e[E_NUM][B_ROWS];     // per-expert row lists
__device__ __align__(16) __half g_wh[6 * 128 * 128];  // 6 weight mats, fp16 row-major

// ============================================================================
// Helpers
// ============================================================================
__device__ __forceinline__ uint32_t smem_to_u32(const void* smem_ptr) {
    uint32_t addr;
    asm("{ .reg .u64 tmp; cvta.to.shared.u64 tmp, %1; cvt.u32.u64 %0, tmp; }"
        : "=r"(addr) : "l"(smem_ptr));
    return addr;
}

__device__ __forceinline__ uint32_t pack_half2(float a, float b) {
    __half2 h = __floats2half2_rn(a, b);
    uint32_t u;
    memcpy(&u, &h, 4);
    return u;
}

#define LDMATRIX_X4(r0, r1, r2, r3, addr) \
    asm volatile("ldmatrix.sync.aligned.m8n8.x4.shared.b16 {%0,%1,%2,%3}, [%4];" \
        : "=r"(r0), "=r"(r1), "=r"(r2), "=r"(r3) : "r"(addr))

#define MMA16816(d, a0, a1, a2, a3, b0, b1) \
    asm volatile("mma.sync.aligned.m16n8k16.row.col.f32.f16.f16.f32 " \
        "{%0,%1,%2,%3}, {%4,%5,%6,%7}, {%8,%9}, {%0,%1,%2,%3};" \
        : "+f"((d)[0]), "+f"((d)[1]), "+f"((d)[2]), "+f"((d)[3]) \
        : "r"(a0), "r"(a1), "r"(a2), "r"(a3), "r"(b0), "r"(b1))

// ============================================================================
// Setup kernels
// ============================================================================

// fp32 -> fp16 weight conversion (4 elems/thread) + g_cnt reset.
__global__ void k_wconv(const float* __restrict__ W1, const float* __restrict__ W2) {
    if (blockIdx.x == 0 && threadIdx.x < E_NUM) g_cnt[threadIdx.x] = 0;
    int i = blockIdx.x * 256 + threadIdx.x;   // 0..24575
    int base = i * 4;
    int mat = base >> 14;
    int r = base & 16383;
    int e = mat >> 1;
    const float* src = (mat & 1) ? W2 : W1;
    float4 v = *(const float4*)(src + e * 16384 + r);
    uint2 o;
    o.x = pack_half2(v.x, v.y);
    o.y = pack_half2(v.z, v.w);
    *(uint2*)(g_wh + base) = o;
}

// Single-pass routing: block-aggregated slot reservation per expert.
__global__ void k_route(const int* __restrict__ ch) {
    __shared__ int sc[E_NUM], sbase[E_NUM];
    int tid = threadIdx.x;
    if (tid < E_NUM) sc[tid] = 0;
    __syncthreads();
    int b = blockIdx.x * 256 + tid;
    int e = ch[b];
    int local = atomicAdd(&sc[e], 1);
    __syncthreads();
    if (tid < E_NUM) sbase[tid] = atomicAdd(&g_cnt[tid], sc[tid]);
    __syncthreads();
    g_idx_e[e][sbase[e] + local] = b;
}

// ============================================================================
// Persistent fused MoE kernel.
// 4 warps / CTA; warp w owns rows [32w, 32w+32) of each 128-row tile.
// Two jn-blocks processed together -> 8 independent MMA chains per warp.
// ============================================================================
#define STRIDE_B   272            // bytes per smem weight row (136 halves)
#define SM_B1      0
#define SM_B2      512
#define SM_W1      1024           // 128 x 272B = 34816
#define SM_W2      35840
#define SMEM_TOTAL 70656

__global__ void __launch_bounds__(128, 2) k_moe(
    const float* __restrict__ x,
    const float* __restrict__ b1g,
    const float* __restrict__ b2g,
    const float* __restrict__ fresh,
    float* __restrict__ out)
{
    extern __shared__ char smem[];
    uint32_t sb = smem_to_u32(smem);
    int tid  = threadIdx.x;
    int lane = tid & 31;
    int warp = tid >> 5;

    // inline tile plan from g_cnt
    int cn0 = g_cnt[0], cn1 = g_cnt[1], cn2 = g_cnt[2];
    int n0 = (cn0 + 127) >> 7, n1 = (cn1 + 127) >> 7, n2 = (cn2 + 127) >> 7;
    int ntiles = n0 + n1 + n2;

    int chunk = (ntiles + NCTA - 1) / NCTA;
    int t0 = blockIdx.x * chunk;
    int t1 = min(ntiles, t0 + chunk);
    if (t0 >= t1) return;

    int qrow = lane >> 2;                 // 0..7
    int c0   = 2 * (lane & 3);            // fragment column pair base

    // ldmatrix B addressing (layout validated in R4/R5)
    uint32_t b_row  = (uint32_t)(((lane >> 4) & 1) * 8 + (lane & 7));
    uint32_t b_coff = (uint32_t)(((lane >> 3) & 1) * 16);
    uint32_t b1_base = sb + SM_W1 + b_row * STRIDE_B + b_coff;
    uint32_t b2_base = sb + SM_W2 + b_row * STRIDE_B + b_coff;

    const float* b1s = (const float*)(smem + SM_B1);
    const float* b2s = (const float*)(smem + SM_B2);

    int cur_e = -1;
    float factor = 1.0f;

    for (int t = t0; t < t1; t++) {
        // tile -> (expert, local base, rows)
        int e, l, cnt;
        if (t < n0)           { e = 0; l = t;            cnt = cn0; }
        else if (t < n0 + n1) { e = 1; l = t - n0;       cnt = cn1; }
        else                  { e = 2; l = t - n0 - n1;  cnt = cn2; }
        int lbase = l * 128;
        int m = min(128, cnt - lbase);

        if (e != cur_e) {
            __syncthreads();   // drain warps still reading old W
            const int4* ws1 = (const int4*)(g_wh + (e * 2 + 0) * 16384);
            const int4* ws2 = (const int4*)(g_wh + (e * 2 + 1) * 16384);
            #pragma unroll
            for (int i = tid; i < 2048; i += 128) {
                int row = i >> 4, ch = i & 15;
                *(int4*)(smem + SM_W1 + row * STRIDE_B + ch * 16) = ws1[i];
                *(int4*)(smem + SM_W2 + row * STRIDE_B + ch * 16) = ws2[i];
            }
            if (tid < 128) {
                ((float*)(smem + SM_B1))[tid] = b1g[e * 128 + tid];
                ((float*)(smem + SM_B2))[tid] = b2g[e * 128 + tid];
            }
            factor = (fresh[e] > 0.f) ? 1.01f : 1.0f;
            cur_e = e;
            __syncthreads();
        }

        const int* idxp = g_idx_e[e] + lbase;
        int rA0 = warp * 32 + qrow;
        int g0 = (rA0 < m)      ? idxp[rA0]      : -1;   // R0 rowA
        int g1 = (rA0 + 8 < m)  ? idxp[rA0 + 8]  : -1;   // R0 rowB
        int g2 = (rA0 + 16 < m) ? idxp[rA0 + 16] : -1;   // R1 rowA
        int g3 = (rA0 + 24 < m) ? idxp[rA0 + 24] : -1;   // R1 rowB

        // --- gather X into A fragments ---
        uint32_t Xh[2][32];
        {
            int gs[4] = {g0, g1, g2, g3};
            #pragma unroll
            for (int rr = 0; rr < 4; rr++) {
                int R = rr >> 1, o = (rr & 1) * 2;
                int g = gs[rr];
                if (g >= 0) {
                    const float* p = x + (size_t)g * 128 + c0;
                    #pragma unroll
                    for (int ks = 0; ks < 8; ks++) {
                        float2 v0 = *(const float2*)(p + 16 * ks);
                        float2 v1 = *(const float2*)(p + 16 * ks + 8);
                        Xh[R][4 * ks + o]     = pack_half2(v0.x, v0.y);
                        Xh[R][4 * ks + o + 1] = pack_half2(v1.x, v1.y);
                    }
                } else {
                    #pragma unroll
                    for (int ks = 0; ks < 8; ks++) {
                        Xh[R][4 * ks + o] = 0;
                        Xh[R][4 * ks + o + 1] = 0;
                    }
                }
            }
        }

        // ======================= layer 1 -> Hh =======================
        // 2 jn-blocks per iteration: 8 independent accumulator chains.
        uint32_t Hh[2][32];
        #pragma unroll
        for (int jp = 0; jp < 4; jp++) {
            int jnA = 2 * jp, jnB = 2 * jp + 1;
            float acc[8][4];   // [0..3]=jnA {R0n0,R0n1,R1n0,R1n1}, [4..7]=jnB
            #pragma unroll
            for (int a = 0; a < 8; a++)
                #pragma unroll
                for (int q = 0; q < 4; q++) acc[a][q] = 0.f;

            #pragma unroll
            for (int ks = 0; ks < 8; ks++) {
                uint32_t r0, r1, r2, r3, s0, s1, s2, s3;
                LDMATRIX_X4(r0, r1, r2, r3, b1_base + (uint32_t)jnA * (16 * STRIDE_B) + ks * 32);
                LDMATRIX_X4(s0, s1, s2, s3, b1_base + (uint32_t)jnB * (16 * STRIDE_B) + ks * 32);
                uint32_t a00 = Xh[0][4 * ks], a01 = Xh[0][4 * ks + 2], a02 = Xh[0][4 * ks + 1], a03 = Xh[0][4 * ks + 3];
                uint32_t a10 = Xh[1][4 * ks], a11 = Xh[1][4 * ks + 2], a12 = Xh[1][4 * ks + 1], a13 = Xh[1][4 * ks + 3];
                MMA16816(acc[0], a00, a01, a02, a03, r0, r1);
                MMA16816(acc[4], a00, a01, a02, a03, s0, s1);
                MMA16816(acc[2], a10, a11, a12, a13, r0, r1);
                MMA16816(acc[6], a10, a11, a12, a13, s0, s1);
                MMA16816(acc[1], a00, a01, a02, a03, r2, r3);
                MMA16816(acc[5], a00, a01, a02, a03, s2, s3);
                MMA16816(acc[3], a10, a11, a12, a13, r2, r3);
                MMA16816(acc[7], a10, a11, a12, a13, s2, s3);
            }
            // epilogue: relu(+b1) -> layer-2 A fragments (k-groups jnA, jnB)
            #pragma unroll
            for (int h = 0; h < 2; h++) {
                int jn = 2 * jp + h;
                const float* bp = b1s + 16 * jn;
                float2 bb0 = *(const float2*)(bp + c0);
                float2 bb1 = *(const float2*)(bp + 8 + c0);
                float (*ac)[4] = &acc[4 * h];
                #pragma unroll
                for (int R = 0; R < 2; R++) {
                    Hh[R][4 * jn]     = pack_half2(fmaxf(ac[2 * R][0] + bb0.x, 0.f),
                                                   fmaxf(ac[2 * R][1] + bb0.y, 0.f));
                    Hh[R][4 * jn + 1] = pack_half2(fmaxf(ac[2 * R + 1][0] + bb1.x, 0.f),
                                                   fmaxf(ac[2 * R + 1][1] + bb1.y, 0.f));
                    Hh[R][4 * jn + 2] = pack_half2(fmaxf(ac[2 * R][2] + bb0.x, 0.f),
                                                   fmaxf(ac[2 * R][3] + bb0.y, 0.f));
                    Hh[R][4 * jn + 3] = pack_half2(fmaxf(ac[2 * R + 1][2] + bb1.x, 0.f),
                                                   fmaxf(ac[2 * R + 1][3] + bb1.y, 0.f));
                }
            }
        }

        // ======================= layer 2 -> gmem =======================
        float f = factor;
        #pragma unroll
        for (int jp = 0; jp < 4; jp++) {
            int jnA = 2 * jp, jnB = 2 * jp + 1;
            float acc[8][4];
            #pragma unroll
            for (int a = 0; a < 8; a++)
                #pragma unroll
                for (int q = 0; q < 4; q++) acc[a][q] = 0.f;

            #pragma unroll
            for (int ks = 0; ks < 8; ks++) {
                uint32_t r0, r1, r2, r3, s0, s1, s2, s3;
                LDMATRIX_X4(r0, r1, r2, r3, b2_base + (uint32_t)jnA * (16 * STRIDE_B) + ks * 32);
                LDMATRIX_X4(s0, s1, s2, s3, b2_base + (uint32_t)jnB * (16 * STRIDE_B) + ks * 32);
                uint32_t a00 = Hh[0][4 * ks], a01 = Hh[0][4 * ks + 2], a02 = Hh[0][4 * ks + 1], a03 = Hh[0][4 * ks + 3];
                uint32_t a10 = Hh[1][4 * ks], a11 = Hh[1][4 * ks + 2], a12 = Hh[1][4 * ks + 1], a13 = Hh[1][4 * ks + 3];
                MMA16816(acc[0], a00, a01, a02, a03, r0, r1);
                MMA16816(acc[4], a00, a01, a02, a03, s0, s1);
                MMA16816(acc[2], a10, a11, a12, a13, r0, r1);
                MMA16816(acc[6], a10, a11, a12, a13, s0, s1);
                MMA16816(acc[1], a00, a01, a02, a03, r2, r3);
                MMA16816(acc[5], a00, a01, a02, a03, s2, s3);
                MMA16816(acc[3], a10, a11, a12, a13, r2, r3);
                MMA16816(acc[7], a10, a11, a12, a13, s2, s3);
            }
            // epilogue: relu(+b2)*factor -> scatter from registers
            #pragma unroll
            for (int h = 0; h < 2; h++) {
                int jn = 2 * jp + h;
                int col0 = 16 * jn + c0;
                int col1 = col0 + 8;
                float2 bb0 = *(const float2*)(b2s + col0);
                float2 bb1 = *(const float2*)(b2s + col1);
                float (*ac)[4] = &acc[4 * h];
                if (g0 >= 0) {
                    float2 o;
                    o.x = fmaxf(ac[0][0] + bb0.x, 0.f) * f;
                    o.y = fmaxf(ac[0][1] + bb0.y, 0.f) * f;
                    *(float2*)(out + (size_t)g0 * 128 + col0) = o;
                    o.x = fmaxf(ac[1][0] + bb1.x, 0.f) * f;
                    o.y = fmaxf(ac[1][1] + bb1.y, 0.f) * f;
                    *(float2*)(out + (size_t)g0 * 128 + col1) = o;
                }
                if (g1 >= 0) {
                    float2 o;
                    o.x = fmaxf(ac[0][2] + bb0.x, 0.f) * f;
                    o.y = fmaxf(ac[0][3] + bb0.y, 0.f) * f;
                    *(float2*)(out + (size_t)g1 * 128 + col0) = o;
                    o.x = fmaxf(ac[1][2] + bb1.x, 0.f) * f;
                    o.y = fmaxf(ac[1][3] + bb1.y, 0.f) * f;
                    *(float2*)(out + (size_t)g1 * 128 + col1) = o;
                }
                if (g2 >= 0) {
                    float2 o;
                    o.x = fmaxf(ac[2][0] + bb0.x, 0.f) * f;
                    o.y = fmaxf(ac[2][1] + bb0.y, 0.f) * f;
                    *(float2*)(out + (size_t)g2 * 128 + col0) = o;
                    o.x = fmaxf(ac[3][0] + bb1.x, 0.f) * f;
                    o.y = fmaxf(ac[3][1] + bb1.y, 0.f) * f;
                    *(float2*)(out + (size_t)g2 * 128 + col1) = o;
                }
                if (g3 >= 0) {
                    float2 o;
                    o.x = fmaxf(ac[2][2] + bb0.x, 0.f) * f;
                    o.y = fmaxf(ac[2][3] + bb0.y, 0.f) * f;
                    *(float2*)(out + (size_t)g3 * 128 + col0) = o;
                    o.x = fmaxf(ac[3][2] + bb1.x, 0.f) * f;
                    o.y = fmaxf(ac[3][3] + bb1.y, 0.f) * f;
                    *(float2*)(out + (size_t)g3 * 128 + col1) = o;
                }
            }
        }
    }
}

// ============================================================================
// Launcher
// ============================================================================
extern "C" void kernel_launch(void* const* d_in, const int* in_sizes, int n_in,
                              void* d_out, int out_size) {
    const float* x      = (const float*)d_in[0];
    const float* W1     = (const float*)d_in[1];
    const float* b1     = (const float*)d_in[2];
    const float* W2     = (const float*)d_in[3];
    const float* b2     = (const float*)d_in[4];
    const float* fresh  = (const float*)d_in[5];
    const int*   chosen = (const int*)d_in[6];
    float* out = (float*)d_out;

    cudaFuncSetAttribute(k_moe, cudaFuncAttributeMaxDynamicSharedMemorySize, SMEM_TOTAL);

    k_wconv<<<96, 256>>>(W1, W2);          // also resets g_cnt
    k_route<<<B_ROWS / 256, 256>>>(chosen);
    k_moe<<<NCTA, 128, SMEM_TOTAL>>>(x, b1, b2, fresh, out);
}